// round 3
// baseline (speedup 1.0000x reference)
#include <cuda_runtime.h>
#include <math.h>

// Shapes (fixed by the problem)
//  emb_in [512,768], W1 [256,1536], b1[256], W2 [256,256], b2[256], W3[1,256], b3[1]
#define B_ROWS 512
#define D_DIM  768
#define H_DIM  256
#define N_CON  128      // n = B/4
#define M_POS  256      // m = B/2
#define NPAIRS 57280.0f

// ---------------- device scratch (statically allocated: no cudaMalloc) -----
__device__ float g_z[B_ROWS * D_DIM];      // normalized rows
__device__ float g_W1T[2 * D_DIM * H_DIM]; // W1 transposed: [1536][256]
__device__ float g_W2T[H_DIM * H_DIM];     // W2 transposed: [256][256]
__device__ float g_A[N_CON * H_DIM];       // z[:128] @ W1a.T
__device__ float g_B[B_ROWS * H_DIM];      // z @ W1b.T
__device__ float g_cpart[N_CON];           // contrastive partials per i
__device__ float g_epart[8 * N_CON];       // bce partials per pair-block

// ---------------- packed f32x2 helpers -------------------------------------
__device__ __forceinline__ unsigned long long pack2(float x, float y) {
    unsigned long long r;
    asm("mov.b64 %0, {%1, %2};" : "=l"(r) : "f"(x), "f"(y));
    return r;
}
__device__ __forceinline__ void fma2(unsigned long long& acc,
                                     unsigned long long a,
                                     unsigned long long b) {
    asm("fma.rn.f32x2 %0, %1, %2, %0;" : "+l"(acc) : "l"(a), "l"(b));
}
__device__ __forceinline__ float2 unpack2(unsigned long long v) {
    float2 f;
    asm("mov.b64 {%0, %1}, %2;" : "=f"(f.x), "=f"(f.y) : "l"(v));
    return f;
}

// ---------------- kernel 1: L2 normalize rows -------------------------------
__global__ __launch_bounds__(256) void normalize_kernel(const float* __restrict__ emb) {
    int row = blockIdx.x, tid = threadIdx.x, lane = tid & 31, wid = tid >> 5;
    const float* r = emb + row * D_DIM;
    float s = 0.f;
    for (int k = tid; k < D_DIM; k += 256) { float v = r[k]; s += v * v; }
    #pragma unroll
    for (int o = 16; o; o >>= 1) s += __shfl_xor_sync(0xffffffffu, s, o);
    __shared__ float red[8];
    __shared__ float rn;
    if (lane == 0) red[wid] = s;
    __syncthreads();
    if (tid == 0) {
        float t = 0.f;
        #pragma unroll
        for (int w = 0; w < 8; ++w) t += red[w];
        rn = 1.0f / fmaxf(sqrtf(t), 1e-12f);
    }
    __syncthreads();
    float rnv = rn;
    for (int k = tid; k < D_DIM; k += 256) g_z[row * D_DIM + k] = r[k] * rnv;
}

// ---------------- kernel 2: transpose W1, W2 --------------------------------
__global__ __launch_bounds__(256) void transpose_kernel(const float* __restrict__ W1,
                                                        const float* __restrict__ W2) {
    int k = blockIdx.x, tid = threadIdx.x;
    if (k < 2 * D_DIM) {
        g_W1T[k * H_DIM + tid] = W1[tid * (2 * D_DIM) + k];
    } else {
        int kk = k - 2 * D_DIM;
        g_W2T[kk * H_DIM + tid] = W2[tid * H_DIM + kk];
    }
}

// ---------------- kernel 3: contrastive per-row -----------------------------
// cpart[i] = (n-1-i)*log(sum_{k!=i} exp(2 S[i,k])) - sum_{j in (i,128)} 2 S[i,j]
__global__ __launch_bounds__(256) void contrastive_kernel() {
    __shared__ float zi[D_DIM];
    __shared__ float wden[8], wls[8];
    int i = blockIdx.x, tid = threadIdx.x, lane = tid & 31, wid = tid >> 5;
    for (int k = tid; k < D_DIM; k += 256) zi[k] = g_z[i * D_DIM + k];
    __syncthreads();
    float den = 0.f, ls = 0.f;
    for (int j = wid; j < B_ROWS; j += 8) {
        float s = 0.f;
        #pragma unroll
        for (int t = 0; t < D_DIM / 32; ++t) {
            int k = lane + t * 32;
            s += g_z[j * D_DIM + k] * zi[k];
        }
        #pragma unroll
        for (int o = 16; o; o >>= 1) s += __shfl_xor_sync(0xffffffffu, s, o);
        float l = 2.0f * s;
        if (j != i) den += expf(l);
        if (j > i && j < N_CON) ls += l;
    }
    if (lane == 0) { wden[wid] = den; wls[wid] = ls; }
    __syncthreads();
    if (tid == 0) {
        float d = 0.f, L = 0.f;
        #pragma unroll
        for (int w = 0; w < 8; ++w) { d += wden[w]; L += wls[w]; }
        g_cpart[i] = (float)(N_CON - 1 - i) * logf(d) - L;
    }
}

// ---------------- kernel 4: projection A/B ----------------------------------
// rows 0..511  -> g_B[r]  = z[r]   @ W1 cols [768:1536)
// rows 512..639-> g_A[r-512] = z[r-512] @ W1 cols [0:768)
__global__ __launch_bounds__(256) void proj_kernel() {
    __shared__ float zs[8][D_DIM];
    int b = blockIdx.x, tid = threadIdx.x;
    int row0 = b * 8;
    for (int idx = tid; idx < 8 * D_DIM; idx += 256) {
        int rl = idx / D_DIM, k = idx - rl * D_DIM;
        int rg = row0 + rl;
        int zr = (rg < B_ROWS) ? rg : (rg - B_ROWS);
        zs[rl][k] = g_z[zr * D_DIM + k];
    }
    __syncthreads();
    int off = (b < 64) ? D_DIM : 0;   // first 64 blocks compute B (W1b), rest A (W1a)
    float acc[8];
    #pragma unroll
    for (int rl = 0; rl < 8; ++rl) acc[rl] = 0.f;
    #pragma unroll 4
    for (int k = 0; k < D_DIM; ++k) {
        float w = g_W1T[(off + k) * H_DIM + tid];
        #pragma unroll
        for (int rl = 0; rl < 8; ++rl) acc[rl] += w * zs[rl][k];
    }
    #pragma unroll
    for (int rl = 0; rl < 8; ++rl) {
        int rg = row0 + rl;
        if (b < 64) g_B[rg * H_DIM + tid] = acc[rl];
        else        g_A[(rg - B_ROWS) * H_DIM + tid] = acc[rl];
    }
}

// ---------------- kernel 5: pair MLP (dominant cost) ------------------------
// Block (c, i): pairs (i, j) with j in [64c, 64c+64) & j > i.
// h1 packed f32x2 in smem; h2 via fma.rn.f32x2 with W2T staged in smem.
#define PAIR_SMEM (65536 + 32768 + 2048 + 256)
__global__ __launch_bounds__(256, 2) void pair_kernel(const float* __restrict__ b1,
                                                      const float* __restrict__ b2,
                                                      const float* __restrict__ W3,
                                                      const float* __restrict__ b3) {
    extern __shared__ unsigned char smem[];
    unsigned long long (*h1s)[H_DIM] = (unsigned long long (*)[H_DIM])smem;      // [32][256] 64KB
    float (*wtile)[H_DIM] = (float (*)[H_DIM])(smem + 65536);                     // [32][256] 32KB
    float (*wpart)[64]    = (float (*)[64])(smem + 65536 + 32768);                // [8][64]
    float* bces           = (float*)(smem + 65536 + 32768 + 2048);                // [64]

    int c = blockIdx.x, i = blockIdx.y;
    int tid = threadIdx.x, lane = tid & 31, wid = tid >> 5;
    int j0 = c * 64;
    int bid = i * 8 + c;
    if (j0 + 63 <= i) { if (tid == 0) g_epart[bid] = 0.f; return; }

    // build h1 for 64 pairs: thread = neuron k, packed over pair index
    float aibv = g_A[i * H_DIM + tid] + b1[tid];
    #pragma unroll 8
    for (int p2 = 0; p2 < 32; ++p2) {
        int ja = j0 + 2 * p2, jb = ja + 1;
        float va = (ja > i) ? fmaxf(aibv + g_B[ja * H_DIM + tid], 0.f) : 0.f;
        float vb = (jb > i) ? fmaxf(aibv + g_B[jb * H_DIM + tid], 0.f) : 0.f;
        h1s[p2][tid] = pack2(va, vb);
    }
    __syncthreads();

    unsigned long long acc[32];
    #pragma unroll
    for (int p2 = 0; p2 < 32; ++p2) acc[p2] = 0ull;

    for (int kc = 0; kc < 8; ++kc) {
        // stage W2T rows [kc*32, kc*32+32) — contiguous, coalesced
        const float4* src = (const float4*)(g_W2T + kc * 32 * H_DIM);
        float4* dst = (float4*)wtile;
        #pragma unroll
        for (int t = 0; t < 8; ++t) dst[tid + t * 256] = src[tid + t * 256];
        __syncthreads();
        #pragma unroll 4
        for (int kk = 0; kk < 32; kk += 2) {
            float w0 = wtile[kk][tid], w1 = wtile[kk + 1][tid];
            unsigned long long w0p = pack2(w0, w0);
            unsigned long long w1p = pack2(w1, w1);
            int k = kc * 32 + kk;
            #pragma unroll
            for (int p2 = 0; p2 < 32; ++p2) {
                ulonglong2 hv = *reinterpret_cast<const ulonglong2*>(&h1s[p2][k]);
                fma2(acc[p2], hv.x, w0p);
                fma2(acc[p2], hv.y, w1p);
            }
        }
        __syncthreads();
    }

    // epilogue: relu + b2, dot with W3, reduce across 256 neurons per pair
    float b2v = b2[tid], w3v = W3[tid];
    #pragma unroll
    for (int p2 = 0; p2 < 32; ++p2) {
        float2 a = unpack2(acc[p2]);
        float v0 = w3v * fmaxf(a.x + b2v, 0.f);
        float v1 = w3v * fmaxf(a.y + b2v, 0.f);
        #pragma unroll
        for (int o = 16; o; o >>= 1) {
            v0 += __shfl_xor_sync(0xffffffffu, v0, o);
            v1 += __shfl_xor_sync(0xffffffffu, v1, o);
        }
        int p0 = 2 * p2, p1 = p0 + 1;
        if (lane == (p0 & 31)) wpart[wid][p0] = v0;
        if (lane == (p1 & 31)) wpart[wid][p1] = v1;
    }
    __syncthreads();
    if (tid < 64) {
        int p = tid, j = j0 + p;
        float l = b3[0];
        #pragma unroll
        for (int w = 0; w < 8; ++w) l += wpart[w][p];
        float bce = 0.f;
        if (j > i) {
            float y = (j < M_POS) ? 1.f : 0.f;
            bce = fmaxf(l, 0.f) - l * y + log1pf(expf(-fabsf(l)));
        }
        bces[p] = bce;
    }
    __syncthreads();
    if (tid == 0) {
        float s = 0.f;
        for (int p = 0; p < 64; ++p) s += bces[p];
        g_epart[bid] = s;
    }
}

// ---------------- kernel 6: final reduction ---------------------------------
__global__ __launch_bounds__(256) void final_kernel(float* __restrict__ out) {
    __shared__ float red[256];
    int tid = threadIdx.x;
    float e = 0.f;
    for (int idx = tid; idx < 8 * N_CON; idx += 256) e += g_epart[idx];
    red[tid] = e;
    __syncthreads();
    for (int s = 128; s; s >>= 1) {
        if (tid < s) red[tid] += red[tid + s];
        __syncthreads();
    }
    float esum = red[0];
    __syncthreads();
    red[tid] = (tid < N_CON) ? g_cpart[tid] : 0.f;
    __syncthreads();
    for (int s = 128; s; s >>= 1) {
        if (tid < s) red[tid] += red[tid + s];
        __syncthreads();
    }
    if (tid == 0) {
        float closs = -1.984375f * red[0];        // -2*(n-1)/n * closs_sum
        out[0] = closs + esum * (1.0f / NPAIRS);  // + mean BCE
    }
}

// ---------------- launch -----------------------------------------------------
extern "C" void kernel_launch(void* const* d_in, const int* in_sizes, int n_in,
                              void* d_out, int out_size) {
    const float* emb = (const float*)d_in[0];
    const float* W1  = (const float*)d_in[1];
    const float* b1  = (const float*)d_in[2];
    const float* W2  = (const float*)d_in[3];
    const float* b2  = (const float*)d_in[4];
    const float* W3  = (const float*)d_in[5];
    const float* b3  = (const float*)d_in[6];
    float* out = (float*)d_out;

    // Opt-in to >48KB dynamic smem (non-stream API; legal under graph capture).
    cudaFuncSetAttribute(pair_kernel, cudaFuncAttributeMaxDynamicSharedMemorySize, PAIR_SMEM);

    normalize_kernel<<<B_ROWS, 256>>>(emb);
    transpose_kernel<<<2 * D_DIM + H_DIM, 256>>>(W1, W2);
    contrastive_kernel<<<N_CON, 256>>>();
    proj_kernel<<<80, 256>>>();
    pair_kernel<<<dim3(8, N_CON), 256, PAIR_SMEM>>>(b1, b2, W3, b3);
    final_kernel<<<1, 256>>>(out);
}

// round 4
// speedup vs baseline: 1.0689x; 1.0689x over previous
#include <cuda_runtime.h>
#include <math.h>

// Shapes (fixed by the problem)
//  emb_in [512,768], W1 [256,1536], b1[256], W2 [256,256], b2[256], W3[1,256], b3[1]
#define B_ROWS 512
#define D_DIM  768
#define H_DIM  256
#define N_CON  128      // n = B/4
#define M_POS  256      // m = B/2
#define NPAIRS 57280.0f

// ---------------- device scratch (statically allocated: no cudaMalloc) -----
__device__ float g_z[B_ROWS * D_DIM];      // normalized rows
__device__ float g_W1T[2 * D_DIM * H_DIM]; // W1 transposed: [1536][256]
__device__ float g_W2T[H_DIM * H_DIM];     // W2 transposed: [256][256]
__device__ float g_A[N_CON * H_DIM];       // z[:128] @ W1a.T
__device__ float g_B[B_ROWS * H_DIM];      // z @ W1b.T
__device__ float g_cpart[N_CON];           // contrastive partials per i
__device__ float g_epart[8 * N_CON];       // bce partials per pair-block

// ---------------- packed f32x2 helpers -------------------------------------
__device__ __forceinline__ unsigned long long pack2(float x, float y) {
    unsigned long long r;
    asm("mov.b64 %0, {%1, %2};" : "=l"(r) : "f"(x), "f"(y));
    return r;
}
__device__ __forceinline__ void fma2(unsigned long long& acc,
                                     unsigned long long a,
                                     unsigned long long b) {
    asm("fma.rn.f32x2 %0, %1, %2, %0;" : "+l"(acc) : "l"(a), "l"(b));
}
__device__ __forceinline__ float2 unpack2(unsigned long long v) {
    float2 f;
    asm("mov.b64 {%0, %1}, %2;" : "=f"(f.x), "=f"(f.y) : "l"(v));
    return f;
}

// ---------------- kernel 1: L2 normalize rows -------------------------------
__global__ __launch_bounds__(256) void normalize_kernel(const float* __restrict__ emb) {
    int row = blockIdx.x, tid = threadIdx.x, lane = tid & 31, wid = tid >> 5;
    const float* r = emb + row * D_DIM;
    float s = 0.f;
    for (int k = tid; k < D_DIM; k += 256) { float v = r[k]; s += v * v; }
    #pragma unroll
    for (int o = 16; o; o >>= 1) s += __shfl_xor_sync(0xffffffffu, s, o);
    __shared__ float red[8];
    __shared__ float rn;
    if (lane == 0) red[wid] = s;
    __syncthreads();
    if (tid == 0) {
        float t = 0.f;
        #pragma unroll
        for (int w = 0; w < 8; ++w) t += red[w];
        rn = 1.0f / fmaxf(sqrtf(t), 1e-12f);
    }
    __syncthreads();
    float rnv = rn;
    for (int k = tid; k < D_DIM; k += 256) g_z[row * D_DIM + k] = r[k] * rnv;
}

// ---------------- kernel 2: transpose W1, W2 --------------------------------
__global__ __launch_bounds__(256) void transpose_kernel(const float* __restrict__ W1,
                                                        const float* __restrict__ W2) {
    int k = blockIdx.x, tid = threadIdx.x;
    if (k < 2 * D_DIM) {
        g_W1T[k * H_DIM + tid] = W1[tid * (2 * D_DIM) + k];
    } else {
        int kk = k - 2 * D_DIM;
        g_W2T[kk * H_DIM + tid] = W2[tid * H_DIM + kk];
    }
}

// ---------------- kernel 3: contrastive per-row -----------------------------
// cpart[i] = (n-1-i)*log(sum_{k!=i} exp(2 S[i,k])) - sum_{j in (i,128)} 2 S[i,j]
__global__ __launch_bounds__(256) void contrastive_kernel() {
    __shared__ float zi[D_DIM];
    __shared__ float wden[8], wls[8];
    int i = blockIdx.x, tid = threadIdx.x, lane = tid & 31, wid = tid >> 5;
    for (int k = tid; k < D_DIM; k += 256) zi[k] = g_z[i * D_DIM + k];
    __syncthreads();
    float den = 0.f, ls = 0.f;
    for (int j = wid; j < B_ROWS; j += 8) {
        float s = 0.f;
        #pragma unroll
        for (int t = 0; t < D_DIM / 32; ++t) {
            int k = lane + t * 32;
            s += g_z[j * D_DIM + k] * zi[k];
        }
        #pragma unroll
        for (int o = 16; o; o >>= 1) s += __shfl_xor_sync(0xffffffffu, s, o);
        float l = 2.0f * s;
        if (j != i) den += expf(l);
        if (j > i && j < N_CON) ls += l;
    }
    if (lane == 0) { wden[wid] = den; wls[wid] = ls; }
    __syncthreads();
    if (tid == 0) {
        float d = 0.f, L = 0.f;
        #pragma unroll
        for (int w = 0; w < 8; ++w) { d += wden[w]; L += wls[w]; }
        g_cpart[i] = (float)(N_CON - 1 - i) * logf(d) - L;
    }
}

// ---------------- kernel 4: projection A/B (smem-staged tile GEMM) ----------
// 160 blocks: rowgrp = b>>1 (8 z-rows), half = b&1 (128 W-cols).
// rowgrp <  64 : g_B[rows rowgrp*8 ..]  = z[rows] @ W1 cols [768:1536)
// rowgrp >= 64 : g_A[rows-512]          = z[rows-512] @ W1 cols [0:768)
__global__ __launch_bounds__(256, 2) void proj_kernel() {
    __shared__ float zs[8][D_DIM];            // 24 KB
    __shared__ float wt[2][32][128];          // 32 KB double-buffered W tile
    int b = blockIdx.x, tid = threadIdx.x;
    int rowgrp = b >> 1, half = b & 1;
    int col = tid & 127;                      // local W-col
    int rsub = tid >> 7;                      // 0: rows 0-3, 1: rows 4-7
    int row0 = rowgrp * 8;
    int off = (rowgrp < 64) ? D_DIM : 0;

    // stage 8 z rows (coalesced float4)
    for (int f = tid; f < 8 * (D_DIM / 4); f += 256) {
        int rl = f / (D_DIM / 4), c4 = f % (D_DIM / 4);
        int rg = row0 + rl;
        int zr = (rg < B_ROWS) ? rg : rg - B_ROWS;
        ((float4*)zs)[f] = ((const float4*)(g_z + zr * D_DIM))[c4];
    }

    float4 pre[4];
    const float* wbase = g_W1T + off * H_DIM + half * 128;
    // prefetch chunk 0
    #pragma unroll
    for (int u = 0; u < 4; ++u) {
        int f = tid + u * 256;                // 0..1023
        int kk = f >> 5, c4 = f & 31;
        pre[u] = *(const float4*)(wbase + kk * H_DIM + c4 * 4);
    }

    float acc[4] = {0.f, 0.f, 0.f, 0.f};
    for (int t = 0; t < D_DIM / 32; ++t) {
        int buf = t & 1;
        #pragma unroll
        for (int u = 0; u < 4; ++u) {
            int f = tid + u * 256;
            int kk = f >> 5, c4 = f & 31;
            *(float4*)(&wt[buf][kk][c4 * 4]) = pre[u];
        }
        __syncthreads();
        if (t + 1 < D_DIM / 32) {
            int k0n = (t + 1) * 32;
            #pragma unroll
            for (int u = 0; u < 4; ++u) {
                int f = tid + u * 256;
                int kk = f >> 5, c4 = f & 31;
                pre[u] = *(const float4*)(wbase + (k0n + kk) * H_DIM + c4 * 4);
            }
        }
        int k0 = t * 32;
        #pragma unroll
        for (int kk = 0; kk < 32; ++kk) {
            float w = wt[buf][kk][col];
            int k = k0 + kk;
            #pragma unroll
            for (int rl = 0; rl < 4; ++rl)
                acc[rl] = fmaf(zs[rsub * 4 + rl][k], w, acc[rl]);
        }
        __syncthreads();
    }

    int outcol = half * 128 + col;
    #pragma unroll
    for (int rl = 0; rl < 4; ++rl) {
        int rg = row0 + rsub * 4 + rl;
        if (rowgrp < 64) g_B[rg * H_DIM + outcol] = acc[rl];
        else             g_A[(rg - B_ROWS) * H_DIM + outcol] = acc[rl];
    }
}

// ---------------- kernel 5: pair MLP (dominant cost) ------------------------
// Block (c, i): pairs (i, j) with j in [64c, 64c+64) & j > i.
// h1 packed f32x2 in smem; h2 via fma.rn.f32x2 with W2T staged in smem.
#define PAIR_SMEM (65536 + 32768 + 2048 + 256)
__global__ __launch_bounds__(256, 2) void pair_kernel(const float* __restrict__ b1,
                                                      const float* __restrict__ b2,
                                                      const float* __restrict__ W3,
                                                      const float* __restrict__ b3) {
    extern __shared__ unsigned char smem[];
    unsigned long long (*h1s)[H_DIM] = (unsigned long long (*)[H_DIM])smem;      // [32][256] 64KB
    float (*wtile)[H_DIM] = (float (*)[H_DIM])(smem + 65536);                     // [32][256] 32KB
    float (*wpart)[64]    = (float (*)[64])(smem + 65536 + 32768);                // [8][64]
    float* bces           = (float*)(smem + 65536 + 32768 + 2048);                // [64]

    int c = blockIdx.x, i = blockIdx.y;
    int tid = threadIdx.x, lane = tid & 31, wid = tid >> 5;
    int j0 = c * 64;
    int bid = i * 8 + c;
    if (j0 + 63 <= i) { if (tid == 0) g_epart[bid] = 0.f; return; }

    // build h1 for 64 pairs: thread = neuron k, packed over pair index
    float aibv = g_A[i * H_DIM + tid] + b1[tid];
    #pragma unroll 8
    for (int p2 = 0; p2 < 32; ++p2) {
        int ja = j0 + 2 * p2, jb = ja + 1;
        float va = (ja > i) ? fmaxf(aibv + g_B[ja * H_DIM + tid], 0.f) : 0.f;
        float vb = (jb > i) ? fmaxf(aibv + g_B[jb * H_DIM + tid], 0.f) : 0.f;
        h1s[p2][tid] = pack2(va, vb);
    }
    __syncthreads();

    unsigned long long acc[32];
    #pragma unroll
    for (int p2 = 0; p2 < 32; ++p2) acc[p2] = 0ull;

    for (int kc = 0; kc < 8; ++kc) {
        // stage W2T rows [kc*32, kc*32+32) — contiguous, coalesced
        const float4* src = (const float4*)(g_W2T + kc * 32 * H_DIM);
        float4* dst = (float4*)wtile;
        #pragma unroll
        for (int t = 0; t < 8; ++t) dst[tid + t * 256] = src[tid + t * 256];
        __syncthreads();
        #pragma unroll 4
        for (int kk = 0; kk < 32; kk += 2) {
            float w0 = wtile[kk][tid], w1 = wtile[kk + 1][tid];
            unsigned long long w0p = pack2(w0, w0);
            unsigned long long w1p = pack2(w1, w1);
            int k = kc * 32 + kk;
            #pragma unroll
            for (int p2 = 0; p2 < 32; ++p2) {
                ulonglong2 hv = *reinterpret_cast<const ulonglong2*>(&h1s[p2][k]);
                fma2(acc[p2], hv.x, w0p);
                fma2(acc[p2], hv.y, w1p);
            }
        }
        __syncthreads();
    }

    // epilogue: relu + b2, dot with W3, reduce across 256 neurons per pair
    float b2v = b2[tid], w3v = W3[tid];
    #pragma unroll
    for (int p2 = 0; p2 < 32; ++p2) {
        float2 a = unpack2(acc[p2]);
        float v0 = w3v * fmaxf(a.x + b2v, 0.f);
        float v1 = w3v * fmaxf(a.y + b2v, 0.f);
        #pragma unroll
        for (int o = 16; o; o >>= 1) {
            v0 += __shfl_xor_sync(0xffffffffu, v0, o);
            v1 += __shfl_xor_sync(0xffffffffu, v1, o);
        }
        int p0 = 2 * p2, p1 = p0 + 1;
        if (lane == (p0 & 31)) wpart[wid][p0] = v0;
        if (lane == (p1 & 31)) wpart[wid][p1] = v1;
    }
    __syncthreads();
    if (tid < 64) {
        int p = tid, j = j0 + p;
        float l = b3[0];
        #pragma unroll
        for (int w = 0; w < 8; ++w) l += wpart[w][p];
        float bce = 0.f;
        if (j > i) {
            float y = (j < M_POS) ? 1.f : 0.f;
            bce = fmaxf(l, 0.f) - l * y + log1pf(expf(-fabsf(l)));
        }
        bces[p] = bce;
    }
    __syncthreads();
    if (tid == 0) {
        float s = 0.f;
        for (int p = 0; p < 64; ++p) s += bces[p];
        g_epart[bid] = s;
    }
}

// ---------------- kernel 6: final reduction ---------------------------------
__global__ __launch_bounds__(256) void final_kernel(float* __restrict__ out) {
    __shared__ float red[256];
    int tid = threadIdx.x;
    float e = 0.f;
    for (int idx = tid; idx < 8 * N_CON; idx += 256) e += g_epart[idx];
    red[tid] = e;
    __syncthreads();
    for (int s = 128; s; s >>= 1) {
        if (tid < s) red[tid] += red[tid + s];
        __syncthreads();
    }
    float esum = red[0];
    __syncthreads();
    red[tid] = (tid < N_CON) ? g_cpart[tid] : 0.f;
    __syncthreads();
    for (int s = 128; s; s >>= 1) {
        if (tid < s) red[tid] += red[tid + s];
        __syncthreads();
    }
    if (tid == 0) {
        float closs = -1.984375f * red[0];        // -2*(n-1)/n * closs_sum
        out[0] = closs + esum * (1.0f / NPAIRS);  // + mean BCE
    }
}

// ---------------- launch -----------------------------------------------------
extern "C" void kernel_launch(void* const* d_in, const int* in_sizes, int n_in,
                              void* d_out, int out_size) {
    const float* emb = (const float*)d_in[0];
    const float* W1  = (const float*)d_in[1];
    const float* b1  = (const float*)d_in[2];
    const float* W2  = (const float*)d_in[3];
    const float* b2  = (const float*)d_in[4];
    const float* W3  = (const float*)d_in[5];
    const float* b3  = (const float*)d_in[6];
    float* out = (float*)d_out;

    // Opt-in to >48KB dynamic smem (non-stream API; legal under graph capture).
    cudaFuncSetAttribute(pair_kernel, cudaFuncAttributeMaxDynamicSharedMemorySize, PAIR_SMEM);

    normalize_kernel<<<B_ROWS, 256>>>(emb);
    transpose_kernel<<<2 * D_DIM + H_DIM, 256>>>(W1, W2);
    contrastive_kernel<<<N_CON, 256>>>();
    proj_kernel<<<160, 256>>>();
    pair_kernel<<<dim3(8, N_CON), 256, PAIR_SMEM>>>(b1, b2, W3, b3);
    final_kernel<<<1, 256>>>(out);
}

// round 6
// speedup vs baseline: 2.6007x; 2.4330x over previous
#include <cuda_runtime.h>
#include <cuda_bf16.h>
#include <math.h>

// Shapes (fixed by the problem)
//  emb_in [512,768], W1 [256,1536], b1[256], W2 [256,256], b2[256], W3[1,256], b3[1]
#define B_ROWS 512
#define D_DIM  768
#define H_DIM  256
#define N_CON  128      // n = B/4
#define M_POS  256      // m = B/2
#define NPAIRS 57280.0f

// ---------------- device scratch (statically allocated: no cudaMalloc) -----
__device__ float g_z[B_ROWS * D_DIM];            // normalized rows (f32)
__device__ float g_W1T[2 * D_DIM * H_DIM];       // W1 transposed: [1536][256] f32
__device__ __nv_bfloat16 g_W2h[H_DIM * H_DIM];   // W2 bf16, natural [n][k]
__device__ __nv_bfloat16 g_Ah[N_CON * H_DIM];    // (z[:128] @ W1a.T + b1) bf16
__device__ __nv_bfloat16 g_Bh[B_ROWS * H_DIM];   // (z @ W1b.T) bf16
__device__ float g_lp[2][N_CON][B_ROWS];         // logit partials per N-half
__device__ float g_cpart[N_CON];                 // contrastive partials per i
__device__ float g_epart[N_CON];                 // bce partials per i

// ---------------- kernel 1: L2 normalize rows -------------------------------
__global__ __launch_bounds__(256) void normalize_kernel(const float* __restrict__ emb) {
    int row = blockIdx.x, tid = threadIdx.x, lane = tid & 31, wid = tid >> 5;
    const float* r = emb + row * D_DIM;
    float s = 0.f;
    for (int k = tid; k < D_DIM; k += 256) { float v = r[k]; s += v * v; }
    #pragma unroll
    for (int o = 16; o; o >>= 1) s += __shfl_xor_sync(0xffffffffu, s, o);
    __shared__ float red[8];
    __shared__ float rn;
    if (lane == 0) red[wid] = s;
    __syncthreads();
    if (tid == 0) {
        float t = 0.f;
        #pragma unroll
        for (int w = 0; w < 8; ++w) t += red[w];
        rn = 1.0f / fmaxf(sqrtf(t), 1e-12f);
    }
    __syncthreads();
    float rnv = rn;
    for (int k = tid; k < D_DIM; k += 256) g_z[row * D_DIM + k] = r[k] * rnv;
}

// ---------------- kernel 2: transpose W1 (f32) + convert W2 (bf16) ----------
__global__ __launch_bounds__(256) void prep_kernel(const float* __restrict__ W1,
                                                   const float* __restrict__ W2) {
    int k = blockIdx.x, tid = threadIdx.x;
    if (k < 2 * D_DIM) {
        g_W1T[k * H_DIM + tid] = W1[tid * (2 * D_DIM) + k];
    } else {
        int n = k - 2 * D_DIM;  // 0..255
        g_W2h[n * H_DIM + tid] = __float2bfloat16(W2[n * H_DIM + tid]);
    }
}

// ---------------- kernel 3: contrastive per-row -----------------------------
// cpart[i] = (n-1-i)*log(sum_{k!=i} exp(2 S[i,k])) - sum_{j in (i,128)} 2 S[i,j]
__global__ __launch_bounds__(256) void contrastive_kernel() {
    __shared__ float zi[D_DIM];
    __shared__ float wden[8], wls[8];
    int i = blockIdx.x, tid = threadIdx.x, lane = tid & 31, wid = tid >> 5;
    for (int k = tid; k < D_DIM; k += 256) zi[k] = g_z[i * D_DIM + k];
    __syncthreads();
    float den = 0.f, ls = 0.f;
    for (int j = wid; j < B_ROWS; j += 8) {
        float s = 0.f;
        #pragma unroll
        for (int t = 0; t < D_DIM / 32; ++t) {
            int k = lane + t * 32;
            s += g_z[j * D_DIM + k] * zi[k];
        }
        #pragma unroll
        for (int o = 16; o; o >>= 1) s += __shfl_xor_sync(0xffffffffu, s, o);
        float l = 2.0f * s;
        if (j != i) den += expf(l);
        if (j > i && j < N_CON) ls += l;
    }
    if (lane == 0) { wden[wid] = den; wls[wid] = ls; }
    __syncthreads();
    if (tid == 0) {
        float d = 0.f, L = 0.f;
        #pragma unroll
        for (int w = 0; w < 8; ++w) { d += wden[w]; L += wls[w]; }
        g_cpart[i] = (float)(N_CON - 1 - i) * logf(d) - L;
    }
}

// ---------------- kernel 4: projection A/B (smem-staged tile GEMM, bf16 out)
// 160 blocks: rowgrp = b>>1 (8 z-rows), half = b&1 (128 W-cols).
// rowgrp <  64 : g_Bh[rows rowgrp*8 ..]       = z[rows] @ W1 cols [768:1536)
// rowgrp >= 64 : g_Ah[rows-512] (+b1 folded)  = z[rows-512] @ W1 cols [0:768)
__global__ __launch_bounds__(256, 2) void proj_kernel(const float* __restrict__ b1) {
    __shared__ float zs[8][D_DIM];            // 24 KB
    __shared__ float wt[2][32][128];          // 32 KB double-buffered W tile
    int b = blockIdx.x, tid = threadIdx.x;
    int rowgrp = b >> 1, half = b & 1;
    int col = tid & 127;
    int rsub = tid >> 7;
    int row0 = rowgrp * 8;
    int off = (rowgrp < 64) ? D_DIM : 0;

    for (int f = tid; f < 8 * (D_DIM / 4); f += 256) {
        int rl = f / (D_DIM / 4), c4 = f % (D_DIM / 4);
        int rg = row0 + rl;
        int zr = (rg < B_ROWS) ? rg : rg - B_ROWS;
        ((float4*)zs)[f] = ((const float4*)(g_z + zr * D_DIM))[c4];
    }

    float4 pre[4];
    const float* wbase = g_W1T + off * H_DIM + half * 128;
    #pragma unroll
    for (int u = 0; u < 4; ++u) {
        int f = tid + u * 256;
        int kk = f >> 5, c4 = f & 31;
        pre[u] = *(const float4*)(wbase + kk * H_DIM + c4 * 4);
    }

    float acc[4] = {0.f, 0.f, 0.f, 0.f};
    for (int t = 0; t < D_DIM / 32; ++t) {
        int buf = t & 1;
        #pragma unroll
        for (int u = 0; u < 4; ++u) {
            int f = tid + u * 256;
            int kk = f >> 5, c4 = f & 31;
            *(float4*)(&wt[buf][kk][c4 * 4]) = pre[u];
        }
        __syncthreads();
        if (t + 1 < D_DIM / 32) {
            int k0n = (t + 1) * 32;
            #pragma unroll
            for (int u = 0; u < 4; ++u) {
                int f = tid + u * 256;
                int kk = f >> 5, c4 = f & 31;
                pre[u] = *(const float4*)(wbase + (k0n + kk) * H_DIM + c4 * 4);
            }
        }
        int k0 = t * 32;
        #pragma unroll
        for (int kk = 0; kk < 32; ++kk) {
            float w = wt[buf][kk][col];
            int k = k0 + kk;
            #pragma unroll
            for (int rl = 0; rl < 4; ++rl)
                acc[rl] = fmaf(zs[rsub * 4 + rl][k], w, acc[rl]);
        }
        __syncthreads();
    }

    int outcol = half * 128 + col;
    float b1v = b1[outcol];
    #pragma unroll
    for (int rl = 0; rl < 4; ++rl) {
        int rg = row0 + rsub * 4 + rl;
        if (rowgrp < 64) g_Bh[rg * H_DIM + outcol] = __float2bfloat16(acc[rl]);
        else             g_Ah[(rg - B_ROWS) * H_DIM + outcol] = __float2bfloat16(acc[rl] + b1v);
    }
}

// ---------------- kernel 5: pair MLP via bf16 mma.sync ----------------------
// Block (c, i, nh): 128 pairs (i, j) with j in [128c, 128c+128), N-half nh.
// h2[p][n] = sum_k h1[p][k] * W2[n][k];  partial logit over this block's 128 n.
#define SM_STRIDE 264   // 256 + 8 bf16 pad -> conflict-free fragment LDS
#define PAIR2_SMEM (2 * 128 * SM_STRIDE * 2)
__global__ __launch_bounds__(256, 1) void pair_mma_kernel(const float* __restrict__ b2,
                                                          const float* __restrict__ W3) {
    extern __shared__ __nv_bfloat16 sm[];
    __nv_bfloat16* h1s = sm;                         // [128][264]
    __nv_bfloat16* w2s = sm + 128 * SM_STRIDE;       // [128][264]

    int c = blockIdx.x, i = blockIdx.y, nh = blockIdx.z;
    int tid = threadIdx.x, lane = tid & 31, wid = tid >> 5;
    int j0 = c * 128;

    // ---- build h1 tile: h1[r][k] = relu(Ah[i][k] + Bh[j0+r][k]) ----
    const __nv_bfloat162* Arow = (const __nv_bfloat162*)(g_Ah + i * H_DIM);
    for (int e = tid; e < 128 * 128; e += 256) {
        int r = e >> 7, kp = e & 127;
        __nv_bfloat162 av = Arow[kp];
        __nv_bfloat162 bv = ((const __nv_bfloat162*)(g_Bh + (j0 + r) * H_DIM))[kp];
        float x = fmaxf(__bfloat162float(av.x) + __bfloat162float(bv.x), 0.f);
        float y = fmaxf(__bfloat162float(av.y) + __bfloat162float(bv.y), 0.f);
        *(__nv_bfloat162*)(h1s + r * SM_STRIDE + 2 * kp) = __floats2bfloat162_rn(x, y);
    }
    // ---- stage W2 half: rows n = nh*128 + r ----
    for (int e = tid; e < 128 * 32; e += 256) {
        int r = e >> 5, q = e & 31;
        uint4 v = ((const uint4*)(g_W2h + (nh * 128 + r) * H_DIM))[q];
        *(uint4*)(w2s + r * SM_STRIDE + q * 8) = v;
    }
    __syncthreads();

    // warp tile: 32 M-rows x 64 N-cols. warps: 4 in M, 2 in N.
    int mw = wid & 3, nw = wid >> 2;
    int g = lane >> 2, tg = lane & 3;

    float acc[2][8][4];
    #pragma unroll
    for (int ms = 0; ms < 2; ++ms)
        #pragma unroll
        for (int ns = 0; ns < 8; ++ns)
            #pragma unroll
            for (int q = 0; q < 4; ++q) acc[ms][ns][q] = 0.f;

    #pragma unroll 2
    for (int ks = 0; ks < 16; ++ks) {
        int k0 = ks * 16;
        unsigned a[2][4];
        #pragma unroll
        for (int ms = 0; ms < 2; ++ms) {
            int r = mw * 32 + ms * 16 + g;
            const __nv_bfloat16* base0 = h1s + r * SM_STRIDE + k0 + 2 * tg;
            const __nv_bfloat16* base8 = base0 + 8 * SM_STRIDE;
            a[ms][0] = *(const unsigned*)(base0);
            a[ms][1] = *(const unsigned*)(base8);
            a[ms][2] = *(const unsigned*)(base0 + 8);
            a[ms][3] = *(const unsigned*)(base8 + 8);
        }
        unsigned bfr[8][2];
        #pragma unroll
        for (int ns = 0; ns < 8; ++ns) {
            int nl = nw * 64 + ns * 8 + g;   // local n (within the 128-half)
            const __nv_bfloat16* bb = w2s + nl * SM_STRIDE + k0 + 2 * tg;
            bfr[ns][0] = *(const unsigned*)(bb);
            bfr[ns][1] = *(const unsigned*)(bb + 8);
        }
        #pragma unroll
        for (int ms = 0; ms < 2; ++ms)
            #pragma unroll
            for (int ns = 0; ns < 8; ++ns) {
                asm volatile(
                    "mma.sync.aligned.m16n8k16.row.col.f32.bf16.bf16.f32 "
                    "{%0,%1,%2,%3}, {%4,%5,%6,%7}, {%8,%9}, {%0,%1,%2,%3};"
                    : "+f"(acc[ms][ns][0]), "+f"(acc[ms][ns][1]),
                      "+f"(acc[ms][ns][2]), "+f"(acc[ms][ns][3])
                    : "r"(a[ms][0]), "r"(a[ms][1]), "r"(a[ms][2]), "r"(a[ms][3]),
                      "r"(bfr[ns][0]), "r"(bfr[ns][1]));
            }
    }

    // ---- epilogue: relu(h2 + b2) dot W3 over this block's n, per pair-row --
    // D frag: d0,d1 -> (row g, cols 2tg,2tg+1); d2,d3 -> (row g+8).
    #pragma unroll
    for (int ms = 0; ms < 2; ++ms) {
        float rs0 = 0.f, rs1 = 0.f;
        #pragma unroll
        for (int ns = 0; ns < 8; ++ns) {
            int n0 = nh * 128 + nw * 64 + ns * 8 + 2 * tg;
            float b20 = __ldg(b2 + n0), b21 = __ldg(b2 + n0 + 1);
            float w30 = __ldg(W3 + n0), w31 = __ldg(W3 + n0 + 1);
            rs0 += fmaxf(acc[ms][ns][0] + b20, 0.f) * w30
                 + fmaxf(acc[ms][ns][1] + b21, 0.f) * w31;
            rs1 += fmaxf(acc[ms][ns][2] + b20, 0.f) * w30
                 + fmaxf(acc[ms][ns][3] + b21, 0.f) * w31;
        }
        // reduce over the 4 lanes sharing the same row (tg = 0..3)
        rs0 += __shfl_xor_sync(0xffffffffu, rs0, 1);
        rs0 += __shfl_xor_sync(0xffffffffu, rs0, 2);
        rs1 += __shfl_xor_sync(0xffffffffu, rs1, 1);
        rs1 += __shfl_xor_sync(0xffffffffu, rs1, 2);
        if (tg == 0) {
            int r = mw * 32 + ms * 16 + g;
            g_lp[nh][i][j0 + r]     = rs0;
            g_lp[nh][i][j0 + r + 8] = rs1;
        }
    }
}

// ---------------- kernel 6: bce over valid pairs ----------------------------
__global__ __launch_bounds__(256) void bce_kernel(const float* __restrict__ b3) {
    __shared__ float red[8];
    int i = blockIdx.x, tid = threadIdx.x, lane = tid & 31, wid = tid >> 5;
    float b3v = b3[0];
    float s = 0.f;
    for (int j = i + 1 + tid; j < B_ROWS; j += 256) {
        float l = b3v + g_lp[0][i][j] + g_lp[1][i][j];
        float y = (j < M_POS) ? 1.f : 0.f;
        s += fmaxf(l, 0.f) - l * y + log1pf(expf(-fabsf(l)));
    }
    #pragma unroll
    for (int o = 16; o; o >>= 1) s += __shfl_xor_sync(0xffffffffu, s, o);
    if (lane == 0) red[wid] = s;
    __syncthreads();
    if (tid == 0) {
        float t = 0.f;
        #pragma unroll
        for (int w = 0; w < 8; ++w) t += red[w];
        g_epart[i] = t;
    }
}

// ---------------- kernel 7: final reduction ---------------------------------
__global__ __launch_bounds__(128) void final_kernel(float* __restrict__ out) {
    __shared__ float red[128];
    int tid = threadIdx.x;
    red[tid] = g_epart[tid];
    __syncthreads();
    for (int s = 64; s; s >>= 1) {
        if (tid < s) red[tid] += red[tid + s];
        __syncthreads();
    }
    float esum = red[0];
    __syncthreads();
    red[tid] = g_cpart[tid];
    __syncthreads();
    for (int s = 64; s; s >>= 1) {
        if (tid < s) red[tid] += red[tid + s];
        __syncthreads();
    }
    if (tid == 0) {
        float closs = -1.984375f * red[0];        // -2*(n-1)/n * closs_sum
        out[0] = closs + esum * (1.0f / NPAIRS);  // + mean BCE
    }
}

// ---------------- launch -----------------------------------------------------
extern "C" void kernel_launch(void* const* d_in, const int* in_sizes, int n_in,
                              void* d_out, int out_size) {
    const float* emb = (const float*)d_in[0];
    const float* W1  = (const float*)d_in[1];
    const float* b1  = (const float*)d_in[2];
    const float* W2  = (const float*)d_in[3];
    const float* b2  = (const float*)d_in[4];
    const float* W3  = (const float*)d_in[5];
    const float* b3  = (const float*)d_in[6];
    float* out = (float*)d_out;

    cudaFuncSetAttribute(pair_mma_kernel, cudaFuncAttributeMaxDynamicSharedMemorySize, PAIR2_SMEM);

    normalize_kernel<<<B_ROWS, 256>>>(emb);
    prep_kernel<<<2 * D_DIM + H_DIM, 256>>>(W1, W2);
    contrastive_kernel<<<N_CON, 256>>>();
    proj_kernel<<<160, 256>>>(b1);
    pair_mma_kernel<<<dim3(4, N_CON, 2), 256, PAIR2_SMEM>>>(b2, W3);
    bce_kernel<<<N_CON, 256>>>(b3);
    final_kernel<<<1, 128>>>(out);
}